// round 14
// baseline (speedup 1.0000x reference)
#include <cuda_runtime.h>
#include <math.h>

// GASPairCopula: GAS(1,1) gaussian-copula ll scan, T=2^20.
// Chunked speculation (W=512 warm-up, contraction 0.99^512 ~ 5.8e-3).
// R9: 128 chains/block (4 warps -> one chain-warp per SMSP, 64 blocks =
// 1 block/SM, no SMSP/MUFU contention), unified 135KB smem span staged
// coalesced by all 128 threads; chain retimed to ~80 cyc/step.

#define T_LEN    (1 << 20)
#define L_CHUNK  128
#define W_WARM   512
#define P_CHAINS (T_LEN / L_CHUNK)                 // 8192
#define CPB      128                               // chains per block
#define NBLK     (P_CHAINS / CPB)                  // 64
#define SPAN     (W_WARM + CPB * L_CHUNK)          // 16896 steps
#define SM_ELEMS (SPAN + (SPAN >> 7) + 4)          // skewed capacity
#define SMEM_BYTES (SM_ELEMS * sizeof(float2))

__device__ float2 g_sp[T_LEN];                     // {sq = x^2+y^2, p = x*y}
__device__ float  g_partial[P_CHAINS];

// ---- MUFU intrinsics ----
__device__ __forceinline__ float mufu_tanh(float x) {
    float r; asm("tanh.approx.f32 %0, %1;" : "=f"(r) : "f"(x)); return r;
}
__device__ __forceinline__ float mufu_rcp(float x) {
    float r; asm("rcp.approx.f32 %0, %1;" : "=f"(r) : "f"(x)); return r;
}
__device__ __forceinline__ float mufu_rsqrt(float x) {
    float r; asm("rsqrt.approx.f32 %0, %1;" : "=f"(r) : "f"(x)); return r;
}
__device__ __forceinline__ float mufu_lg2(float x) {
    float r; asm("lg2.approx.f32 %0, %1;" : "=f"(r) : "f"(x)); return r;
}

__device__ __forceinline__ int sidx(int t) { return t + (t >> 7); }  // bank skew

// ---------------------------------------------------------------------------
// Kernel 1: ndtri + data invariants (2 elems/thread for high occupancy)
// ---------------------------------------------------------------------------
__global__ void prep_kernel(const float* __restrict__ u_data,
                            const float* __restrict__ v_data) {
    int i = blockIdx.x * blockDim.x + threadIdx.x;
    int t0 = i * 2;
    if (t0 >= T_LEN) return;
    float2 u2 = *(const float2*)(u_data + t0);
    float2 v2 = *(const float2*)(v_data + t0);
    float us[2] = {u2.x, u2.y};
    float vs[2] = {v2.x, v2.y};
    #pragma unroll
    for (int k = 0; k < 2; ++k) {
        float u = fminf(fmaxf(us[k], 1e-9f), 1.0f - 1e-9f);
        float v = fminf(fmaxf(vs[k], 1e-9f), 1.0f - 1e-9f);
        float x = normcdfinvf(u);
        float y = normcdfinvf(v);
        g_sp[t0 + k] = make_float2(fmaf(x, x, y * y), x * y);
    }
}

// ---------------------------------------------------------------------------
// One GAS step, retimed (~80 cyc f->f critical path).
// q = s_var + 1e-8 iterated directly; ll unscaled, *-0.5 at the end.
// ---------------------------------------------------------------------------
__device__ __forceinline__ void gas_step(float& f, float& q, float& acc,
                                         bool want_ll,
                                         float sq, float p,
                                         float c0, float A, float B) {
    float th   = mufu_tanh(f);                     // @16
    float fb   = fmaf(B, f, c0);                   // || with tanh
    float rho  = 0.999f * th;                      // @20
    float g    = 0.999f * fmaf(-th, th, 1.0f);     // @24 (off chain)
    float Ag   = A * g;                            // @28 (off chain)
    float D    = fmaf(-rho, rho, 1.00000001f);     // @24: 1 - rho^2 + 1e-8
    float invD = mufu_rcp(D);                      // @40
    float n2p  = -(p + p);                         // data-only
    float z    = fmaf(rho, n2p, sq);               // @28
    float rz   = rho * z;                          // @32
    float rp   = rho + p;                          // @24

    if (want_ll)
        acc += fmaf(mufu_lg2(D), 0.6931472f, fmaf(z, invD, -sq));

    float u      = fmaf(-rz, invD, rp);            // @44
    float dll    = u * invD;                       // @48
    float score  = dll * g;                        // @52
    float Ascore = dll * Ag;                       // @52 (parallel)
    float s2     = score * score;                  // @56
    float qb     = fmaf(0.99f, q, 1e-10f);         // early: q loop-carried
    q = fmaf(0.01f, s2, qb);                       // @60  (= s_var_new + 1e-8)
    float rs = mufu_rsqrt(q);                      // @76
    f = fmaf(Ascore, rs, fb);                      // @80
}

// ---------------------------------------------------------------------------
// Kernel 2: 128 chains per block (4 warps, one per SMSP), 64 blocks.
// Contiguous 16896-step span staged into dynamic smem, coalesced.
// ---------------------------------------------------------------------------
__global__ void scan_kernel(const float* __restrict__ omega_p,
                            const float* __restrict__ A_p,
                            const float* __restrict__ Blogit_p) {
    extern __shared__ float2 sm[];

    int blk  = blockIdx.x;
    int base = blk * CPB * L_CHUNK;                // 16384 per block
    int lo   = base - W_WARM;
    if (lo < 0) lo = 0;                            // block 0 only
    int hi = base + CPB * L_CHUNK;
    int n  = hi - lo;                              // 16384 or 16896

    // Coalesced staging: float4 = 2 float2 steps, skewed store.
    // n/2 is a multiple of 128 -> no remainder handling.
    const float4* src = (const float4*)(g_sp + lo);
    int nf4 = n >> 1;
    #pragma unroll 4
    for (int j4 = threadIdx.x; j4 < nf4; j4 += CPB) {
        float4 w = src[j4];
        int t0 = j4 * 2;
        sm[sidx(t0)]     = make_float2(w.x, w.y);
        sm[sidx(t0 + 1)] = make_float2(w.z, w.w);
    }
    __syncthreads();

    float omega = *omega_p;
    float A     = *A_p;
    float B     = 1.0f / (1.0f + __expf(-*Blogit_p));
    float c0    = omega * (1.0f - B);

    int chain  = blk * CPB + threadIdx.x;
    int start  = chain * L_CHUNK;
    int wstart = start - W_WARM;
    if (wstart < 0) wstart = 0;
    int end = start + L_CHUNK;

    int j      = wstart - lo;
    int jend   = end - lo;
    int jstart = start - lo;                       // ll turns on here

    float f = omega, q = 1.0f + 1e-8f, acc = 0.0f;

    // Register prefetch one 4-step group ahead (LDS lat 29 << ~340 cyc/group).
    float2 d0 = sm[sidx(j)],     d1 = sm[sidx(j + 1)];
    float2 d2 = sm[sidx(j + 2)], d3 = sm[sidx(j + 3)];

    for (; j < jend; j += 4) {
        int jp = j + 4;
        if (jp > jend - 4) jp = jend - 4;          // clamp (redundant reload ok)
        float2 n0 = sm[sidx(jp)],     n1 = sm[sidx(jp + 1)];
        float2 n2 = sm[sidx(jp + 2)], n3 = sm[sidx(jp + 3)];

        gas_step(f, q, acc, j     >= jstart, d0.x, d0.y, c0, A, B);
        gas_step(f, q, acc, j + 1 >= jstart, d1.x, d1.y, c0, A, B);
        gas_step(f, q, acc, j + 2 >= jstart, d2.x, d2.y, c0, A, B);
        gas_step(f, q, acc, j + 3 >= jstart, d3.x, d3.y, c0, A, B);

        d0 = n0; d1 = n1; d2 = n2; d3 = n3;
    }

    g_partial[chain] = -0.5f * acc;
}

// ---------------------------------------------------------------------------
// Kernel 3: deterministic fixed-order reduction
// ---------------------------------------------------------------------------
__global__ void reduce_kernel(float* __restrict__ out) {
    __shared__ double sh[256];
    int tid = threadIdx.x;
    double s = 0.0;
    for (int i = tid; i < P_CHAINS; i += 256)
        s += (double)g_partial[i];
    sh[tid] = s;
    __syncthreads();
    for (int w = 128; w > 0; w >>= 1) {
        if (tid < w) sh[tid] += sh[tid + w];
        __syncthreads();
    }
    if (tid == 0) out[0] = (float)sh[0];
}

// ---------------------------------------------------------------------------
extern "C" void kernel_launch(void* const* d_in, const int* in_sizes, int n_in,
                              void* d_out, int out_size) {
    const float* u      = (const float*)d_in[0];
    const float* v      = (const float*)d_in[1];
    const float* omega  = (const float*)d_in[2];
    const float* A      = (const float*)d_in[3];
    const float* Blogit = (const float*)d_in[4];
    float* out = (float*)d_out;

    // Dynamic smem opt-in (host-side attribute, idempotent, not a stream op).
    cudaFuncSetAttribute(scan_kernel,
                         cudaFuncAttributeMaxDynamicSharedMemorySize,
                         (int)SMEM_BYTES);

    prep_kernel<<<T_LEN / (256 * 2), 256>>>(u, v);
    scan_kernel<<<NBLK, CPB, SMEM_BYTES>>>(omega, A, Blogit);
    reduce_kernel<<<1, 256>>>(out);
}